// round 4
// baseline (speedup 1.0000x reference)
#include <cuda_runtime.h>
#include <cstdint>
#include <math.h>

// SoftPolygon B=32, P=32, 128x128.  out[b,y,x] = sigmoid(min_seg_sq * io)
//
// v3: packed f32x2 mainloop (FFMA2). Each lane owns 4 columns as 2 packed
//     pairs: (lane, lane+32) and (lane+64, lane+96). Per-edge constants are
//     stored duplicated in shared as float2{v,v} so LDS.128 yields packed
//     operands directly. Clamp via scalar cvt.sat on the pair halves
//     (no packed .sat in PTX); min via scalar FMNMX (alu pipe, underused).
//
// Numerical contract: parity bit-identical to reference (integer-threshold
// + XOR-mask construction); distance path continuous => ulp-level error only.

namespace {

constexpr int NB = 32;
constexpr int NP = 32;
constexpr int NH = 128;
constexpr int NW = 128;
constexpr int RPB = 4;     // rows per block (one warp per row)

__device__ __forceinline__ unsigned long long pack2(float lo, float hi) {
    unsigned long long r;
    asm("mov.b64 %0, {%1, %2};" : "=l"(r) : "f"(lo), "f"(hi));
    return r;
}

// Squared point-to-segment distance for a packed pixel pair.
// gxp: packed (gx_lo, gx_hi); constants packed-duplicated.
// Returns the two distances via dlo/dhi.
__device__ __forceinline__ void seg_dist2_pair(
    unsigned long long gxp,
    unsigned long long dxinv2, unsigned long long c02,
    unsigned long long dx2,    unsigned long long x12,
    unsigned long long negdy2, unsigned long long ys12,
    float& dlo, float& dhi)
{
    asm("{\n\t"
        ".reg .b64 t, e, py, q;\n\t"
        ".reg .f32 f0, f1;\n\t"
        "fma.rn.f32x2 t, %2, %3, %4;\n\t"   // dot = gx*dxinv + c0
        "mov.b64 {f0, f1}, t;\n\t"
        "cvt.sat.f32.f32 f0, f0;\n\t"       // t = clamp(dot, 0, 1)
        "cvt.sat.f32.f32 f1, f1;\n\t"
        "mov.b64 t, {f0, f1};\n\t"
        "fma.rn.f32x2 q, t, %5, %6;\n\t"    // px = t*dx + x1
        "sub.rn.f32x2 e, %2, q;\n\t"        // e  = gx - px
        "fma.rn.f32x2 py, t, %7, %8;\n\t"   // py = t*(-dy) + ys1
        "mul.rn.f32x2 q, py, py;\n\t"
        "fma.rn.f32x2 q, e, e, q;\n\t"      // d  = e*e + py*py
        "mov.b64 {%0, %1}, q;\n\t"
        "}"
        : "=f"(dlo), "=f"(dhi)
        : "l"(gxp), "l"(dxinv2), "l"(c02), "l"(dx2), "l"(x12),
          "l"(negdy2), "l"(ys12));
}

__global__ __launch_bounds__(128) void soft_poly_kernel(
    const float* __restrict__ verts,   // (B, P, 2)
    float* __restrict__ out)           // (B, H, W)
{
    const int b    = blockIdx.y;
    const int row0 = blockIdx.x * RPB;
    const int tid  = threadIdx.x;
    const int r    = tid >> 5;         // warp index = local row
    const int lane = tid & 31;
    const int row  = row0 + r;
    const float gy = (float)row;

    __shared__ float vbuf[NP * 2];               // interleaved x,y
    // per (row, edge): 6 packed-duplicated consts = 3 ulonglong2 (48B)
    __shared__ ulonglong2 sE[RPB][NP][3];

    if (tid < NP * 2) vbuf[tid] = verts[(size_t)b * NP * 2 + tid];
    __syncthreads();

    // ---- per-(row, edge) precompute; edge index = lane, done by warp r ----
    unsigned int pm0, pm1, pm2, pm3;  // parity mask; word k covers cols [32k,32k+32)
    {
        const int i  = lane;
        const int jp = (i + NP - 1) & (NP - 1);   // prev vertex (roll +1)
        const int kn = (i + 1) & (NP - 1);        // next vertex (roll -1)
        const float fx = vbuf[2 * i],  fy = vbuf[2 * i + 1];
        const float tx = vbuf[2 * jp], ty = vbuf[2 * jp + 1];
        const float x2 = vbuf[2 * kn], y2 = vbuf[2 * kn + 1];

        // crossing threshold, EXACT reference op order (mul, div, add)
        const bool cond = (fy > gy) != (ty > gy);
        float xint = __fadd_rn(
            __fdiv_rn(__fmul_rn(tx - fx, gy - fy), ty - fy), fx);
        if (!cond) xint = -1.0f;
        // #columns c in [0,128) with (float)c < xint — exact
        const float xc = fminf(fmaxf(ceilf(xint), 0.0f), 128.0f);
        const int ci = (int)xc;

        const int n0 = min(max(ci,      0), 32);
        const int n1 = min(max(ci - 32, 0), 32);
        const int n2 = min(max(ci - 64, 0), 32);
        const int n3 = min(max(ci - 96, 0), 32);
        const unsigned int m0 = (unsigned int)((1ull << n0) - 1ull);
        const unsigned int m1 = (unsigned int)((1ull << n1) - 1ull);
        const unsigned int m2 = (unsigned int)((1ull << n2) - 1ull);
        const unsigned int m3 = (unsigned int)((1ull << n3) - 1ull);
        pm0 = __reduce_xor_sync(0xffffffffu, m0);
        pm1 = __reduce_xor_sync(0xffffffffu, m1);
        pm2 = __reduce_xor_sync(0xffffffffu, m2);
        pm3 = __reduce_xor_sync(0xffffffffu, m3);

        // segment-distance constants for edge (v_i -> v_{i+1})
        const float dx = x2 - fx, dy = y2 - fy;
        const float sq  = dx * dx + dy * dy + 1e-5f;
        const float inv = __fdiv_rn(1.0f, sq);
        const float ys1   = gy - fy;
        const float dxinv = dx * inv;
        const float c0    = (ys1 * dy - fx * dx) * inv;  // dot = gx*dxinv + c0

        float2* f2 = reinterpret_cast<float2*>(&sE[r][i][0]);
        f2[0] = make_float2(dxinv, dxinv);
        f2[1] = make_float2(c0,    c0);
        f2[2] = make_float2(dx,    dx);
        f2[3] = make_float2(fx,    fx);
        f2[4] = make_float2(-dy,  -dy);
        f2[5] = make_float2(ys1,   ys1);
    }
    __syncwarp();   // sE written and read by the same warp

    // ---- mainloop: 2 packed pixel pairs per lane ----
    const float gx0 = (float)lane;
    const unsigned long long gxpA = pack2(gx0,         gx0 + 32.0f);
    const unsigned long long gxpB = pack2(gx0 + 64.0f, gx0 + 96.0f);
    float mn0 = 3.402823466e38f, mn1 = mn0, mn2 = mn0, mn3 = mn0;

#pragma unroll
    for (int i = 0; i < NP; ++i) {
        const ulonglong2 q0 = sE[r][i][0];
        const ulonglong2 q1 = sE[r][i][1];
        const ulonglong2 q2 = sE[r][i][2];

        float dlo, dhi;
        seg_dist2_pair(gxpA, q0.x, q0.y, q1.x, q1.y, q2.x, q2.y, dlo, dhi);
        mn0 = fminf(mn0, dlo);
        mn1 = fminf(mn1, dhi);
        seg_dist2_pair(gxpB, q0.x, q0.y, q1.x, q1.y, q2.x, q2.y, dlo, dhi);
        mn2 = fminf(mn2, dlo);
        mn3 = fminf(mn3, dhi);
    }

    // ---- epilogue: sign from parity mask, sigmoid, store ----
    float* op = out + ((size_t)b * NH + row) * NW + lane;
#define EMIT(PM, MN, K) do {                                         \
        const float io = ((PM >> lane) & 1u) ? 1.0f : -1.0f;         \
        const float x  = (MN) * io;                                  \
        op[(K) * 32] = __fdividef(1.0f, 1.0f + __expf(-x));          \
    } while (0)
    EMIT(pm0, mn0, 0);
    EMIT(pm1, mn1, 1);
    EMIT(pm2, mn2, 2);
    EMIT(pm3, mn3, 3);
#undef EMIT
}

}  // namespace

extern "C" void kernel_launch(void* const* d_in, const int* in_sizes, int n_in,
                              void* d_out, int out_size) {
    const float* verts = (const float*)d_in[0];
    float* out = (float*)d_out;
    dim3 grid(NH / RPB, NB);   // 32 x 32 = 1024 blocks, 4 warps each
    soft_poly_kernel<<<grid, 128>>>(verts, out);
}